// round 6
// baseline (speedup 1.0000x reference)
#include <cuda_runtime.h>

#define NV 32      // nodes per graph
#define NE 256     // edges per graph
#define NH 4       // heads
#define DH 64      // dim per head
#define CC 256     // NH*DH
#define K1 128     // layer-1 input dim
#define K2 64      // layer-2 input dim
#define NT 256     // threads per block
#define NGRAPHS 2048

#define SR4 65     // node-major row stride in float4 (65 ≡ 1 mod 32)
#define STK 36     // k-major stride (floats)
#define STK4 9
#define HNS4 17    // hN stride in float4
#define AMS 33     // Amat row stride in float4 (33 -> conflict-free across v)

struct __align__(16) Smem {
    float xsT[K1 * STK];    // 4608 f : x transposed [k][node]; reused as Amat (32*33*4=4224 f)
    float bufA[NV * SR4 * 4];   // hs, node-major [node][c]
    float bufB[NV * SR4 * 4];   // hd, node-major; overwritten by aggregation
    float hT[DH * STK];     // maxpooled h, k-major (next-GEMM A / readout)
    float hN[NV * HNS4 * 4];// maxpooled h, node-major (pooling gate)
    float logits[NE * NH];  // [e][h]
    float aw[CC];
    float mx[NV * NH];      // [v][h]
    float den[NV * NH];
    float nalpha[NV];
    int esrc[NE];
    int edst[NE];
    int cnt[NV];
    int startv[NV + 1];
};

__device__ __forceinline__ void fma4(float4& acc, float s, const float4 w) {
    acc.x = fmaf(s, w.x, acc.x);
    acc.y = fmaf(s, w.y, acc.y);
    acc.z = fmaf(s, w.z, acc.z);
    acc.w = fmaf(s, w.w, acc.w);
}

// C[32, 256] = A[32, K] @ W[K, 256] + b. A k-major float4 in smem; out node-major.
// W streamed via 8-deep double-buffered register prefetch: the LDGs for k-block
// i+1 are all in flight while block i is consumed, hiding the ~250-cycle L2
// latency (W cannot live in L1: smem carveout is ~223KB of the unified array).
template <int K>
__device__ __forceinline__ void gemm(const float* __restrict__ W,
                                     const float* __restrict__ b,
                                     const float4* __restrict__ A4,
                                     float4* __restrict__ out4, int tid)
{
    const int tr = tid >> 6;
    const int tc = tid & 63;
    const float4* __restrict__ W4 = reinterpret_cast<const float4*>(W) + tc;
    const float4 bias = __ldg(&reinterpret_cast<const float4*>(b)[tc]);
    float4 acc[8];
#pragma unroll
    for (int i = 0; i < 8; i++) acc[i] = bias;

    constexpr int NB = K / 8;          // number of 8-k blocks
    float4 wbuf[2][8];
#pragma unroll
    for (int j = 0; j < 8; j++) wbuf[0][j] = __ldg(&W4[j * 64]);

#pragma unroll
    for (int kb = 0; kb < NB; kb++) {
        const int cur = kb & 1, nxt = cur ^ 1;
        if (kb + 1 < NB) {
#pragma unroll
            for (int j = 0; j < 8; j++)
                wbuf[nxt][j] = __ldg(&W4[((kb + 1) * 8 + j) * 64]);
        }
#pragma unroll
        for (int j = 0; j < 8; j++) {
            const int k = kb * 8 + j;
            const float4 a0 = A4[k * STK4 + tr * 2];
            const float4 a1 = A4[k * STK4 + tr * 2 + 1];
            const float4 w  = wbuf[cur][j];
            fma4(acc[0], a0.x, w); fma4(acc[1], a0.y, w);
            fma4(acc[2], a0.z, w); fma4(acc[3], a0.w, w);
            fma4(acc[4], a1.x, w); fma4(acc[5], a1.y, w);
            fma4(acc[6], a1.z, w); fma4(acc[7], a1.w, w);
        }
    }
#pragma unroll
    for (int i = 0; i < 8; i++) out4[(tr * 8 + i) * SR4 + tc] = acc[i];
}

// GATv2 edge phase. bufA = hs, bufB = hd (node-major). Agg overwrites bufB.
__device__ __forceinline__ void gat_edge_phase(Smem& s, const float* __restrict__ attn, int tid)
{
    s.aw[tid] = __ldg(&attn[tid]);
    __syncthreads();

    float4* bufA4 = reinterpret_cast<float4*>(s.bufA);
    float4* bufB4 = reinterpret_cast<float4*>(s.bufB);
    const float4* aw4 = reinterpret_cast<const float4*>(s.aw);
    float* Amat = s.xsT;                      // aliased: 32 x AMS float4
    float4* Amat4 = reinterpret_cast<float4*>(Amat);

    const int wid = tid >> 5, lane = tid & 31;
    const int eg = lane >> 3;                 // edge slot within warp (0..3)
    const int ln = lane & 7;                  // channel lane (0..7)

    // attention weights for this lane's channel chunks, cached in regs
    float4 awr[8];
#pragma unroll
    for (int c = 0; c < 8; c++) awr[c] = aw4[c * 8 + ln];

    // --- logits: 4 edges per warp pass, 8 lanes per edge (conflict-free 128B rows) ---
#pragma unroll 2
    for (int pass = 0; pass < 8; pass++) {
        const int e = wid * 32 + pass * 4 + eg;
        const int ss = s.esrc[e], dd = s.edst[e];
        const float4* pa = bufA4 + ss * SR4;
        const float4* pb = bufB4 + dd * SR4;
        float part[NH] = {0.f, 0.f, 0.f, 0.f};
#pragma unroll
        for (int c = 0; c < 8; c++) {
            const float4 sa = pa[c * 8 + ln];
            const float4 sb = pb[c * 8 + ln];
            const float4 w  = awr[c];
            const int h = c >> 1;
            float v;
            v = sa.x + sb.x; part[h] = fmaf(w.x, v > 0.f ? v : 0.2f * v, part[h]);
            v = sa.y + sb.y; part[h] = fmaf(w.y, v > 0.f ? v : 0.2f * v, part[h]);
            v = sa.z + sb.z; part[h] = fmaf(w.z, v > 0.f ? v : 0.2f * v, part[h]);
            v = sa.w + sb.w; part[h] = fmaf(w.w, v > 0.f ? v : 0.2f * v, part[h]);
        }
#pragma unroll
        for (int o = 4; o; o >>= 1) {
            part[0] += __shfl_xor_sync(0xffffffffu, part[0], o);
            part[1] += __shfl_xor_sync(0xffffffffu, part[1], o);
            part[2] += __shfl_xor_sync(0xffffffffu, part[2], o);
            part[3] += __shfl_xor_sync(0xffffffffu, part[3], o);
        }
        if (ln == 0)
            *reinterpret_cast<float4*>(&s.logits[e * NH]) =
                make_float4(part[0], part[1], part[2], part[3]);
    }
    __syncthreads();

    // --- per (node, head) max & exp-sum; other half zeroes Amat ---
    if (tid < NV * NH) {
        const int v = tid >> 2, h = tid & 3;
        const int e0 = s.startv[v], e1 = s.startv[v + 1];
        float m = -1e30f;
        for (int j = e0; j < e1; j++) m = fmaxf(m, s.logits[j * NH + h]);
        float d = 0.f;
        for (int j = e0; j < e1; j++) d += __expf(s.logits[j * NH + h] - m);
        s.mx[tid]  = m;
        s.den[tid] = (d == 0.f) ? 1.f : d;
    } else {
        const float4 z = make_float4(0.f, 0.f, 0.f, 0.f);
        for (int i = tid - 128; i < NV * AMS; i += 128) Amat4[i] = z;
    }
    __syncthreads();

    // --- per-edge alpha, scattered into dense Amat[dst][src] (float4 = 4 heads) ---
    {
        const int e = tid;
        const int dd = s.edst[e], ss = s.esrc[e];
        const float4 lg  = *reinterpret_cast<const float4*>(&s.logits[e * NH]);
        const float4 mxv = *reinterpret_cast<const float4*>(&s.mx[dd * NH]);
        const float4 dnv = *reinterpret_cast<const float4*>(&s.den[dd * NH]);
        float* am = Amat + (dd * AMS + ss) * 4;
        atomicAdd(am + 0, __expf(lg.x - mxv.x) / dnv.x);
        atomicAdd(am + 1, __expf(lg.y - mxv.y) / dnv.y);
        atomicAdd(am + 2, __expf(lg.z - mxv.z) / dnv.z);
        atomicAdd(am + 3, __expf(lg.w - mxv.w) / dnv.w);
    }
    __syncthreads();

    // --- dense aggregation: bufB[v] = sum_u Amat[v][u] (per head) * hs[u] ---
    {
        const int v = tid >> 3;        // 32 nodes
        const int l = tid & 7;         // 8 channel lanes
        float4 acc[8];
#pragma unroll
        for (int blk = 0; blk < 8; blk++) acc[blk] = make_float4(0.f, 0.f, 0.f, 0.f);
        const float4* AmV = Amat4 + v * AMS;
        for (int u = 0; u < NV; u++) {
            const float4 a4 = AmV[u];  // alphas for heads 0..3, broadcast across v-lanes
            const bool nz = (a4.x != 0.f) | (a4.y != 0.f) | (a4.z != 0.f) | (a4.w != 0.f);
            if (!__any_sync(0xffffffffu, nz)) continue;
            const float4* p = bufA4 + u * SR4;
#pragma unroll
            for (int blk = 0; blk < 8; blk++) {
                const int h = blk >> 1;
                const float a = (h == 0) ? a4.x : (h == 1) ? a4.y : (h == 2) ? a4.z : a4.w;
                fma4(acc[blk], a, p[blk * 8 + l]);
            }
        }
#pragma unroll
        for (int blk = 0; blk < 8; blk++) bufB4[v * SR4 + blk * 8 + l] = acc[blk];
    }
    __syncthreads();

    // --- head maxpool -> hT[k][v] and hN[v][k] ---
    float4* hN4 = reinterpret_cast<float4*>(s.hN);
    for (int i = tid; i < NV * DH / 4; i += NT) {
        const int v = i >> 4, q = i & 15;
        float4 m = bufB4[v * SR4 + q];
#pragma unroll
        for (int h = 1; h < NH; h++) {
            const float4 t = bufB4[v * SR4 + h * 16 + q];
            m.x = fmaxf(m.x, t.x); m.y = fmaxf(m.y, t.y);
            m.z = fmaxf(m.z, t.z); m.w = fmaxf(m.w, t.w);
        }
        hN4[v * HNS4 + q] = m;
        const int k0 = q * 4;
        s.hT[(k0 + 0) * STK + v] = m.x;
        s.hT[(k0 + 1) * STK + v] = m.y;
        s.hT[(k0 + 2) * STK + v] = m.z;
        s.hT[(k0 + 3) * STK + v] = m.w;
    }
    __syncthreads();
}

__global__ __launch_bounds__(NT, 2)
void gat_fused_kernel(const float* __restrict__ x,
                      const int* __restrict__ src,
                      const int* __restrict__ dst,
                      const float* __restrict__ W1s, const float* __restrict__ b1s,
                      const float* __restrict__ W1d, const float* __restrict__ b1d,
                      const float* __restrict__ a1,
                      const float* __restrict__ W2s, const float* __restrict__ b2s,
                      const float* __restrict__ W2d, const float* __restrict__ b2d,
                      const float* __restrict__ a2,
                      const float* __restrict__ Wg, const float* __restrict__ bg,
                      float* __restrict__ out)
{
    extern __shared__ unsigned char smraw[];
    Smem& s = *reinterpret_cast<Smem*>(smraw);
    const int g = blockIdx.x, tid = threadIdx.x;

    // ---- phase 0: load x transposed, count-sort edges by dst ----
    {
        const float* xg = x + (size_t)g * NV * K1;
        for (int i = tid; i < NV * K1; i += NT) {
            const int row = i >> 7, k = i & 127;
            s.xsT[k * STK + row] = __ldg(&xg[i]);
        }
        const int rs = src[g * NE + tid] - g * NV;
        const int rd = dst[g * NE + tid] - g * NV;
        if (tid < NV) s.cnt[tid] = 0;
        __syncthreads();
        const int p = atomicAdd(&s.cnt[rd], 1);
        __syncthreads();
        if (tid == 0) {
            int acc = 0;
            for (int v = 0; v < NV; v++) { s.startv[v] = acc; acc += s.cnt[v]; }
            s.startv[NV] = acc;
        }
        __syncthreads();
        const int j = s.startv[rd] + p;
        s.esrc[j] = rs;
        s.edst[j] = rd;
    }
    __syncthreads();

    float4* xsT4  = reinterpret_cast<float4*>(s.xsT);
    float4* hT4   = reinterpret_cast<float4*>(s.hT);
    float4* bufA4 = reinterpret_cast<float4*>(s.bufA);
    float4* bufB4 = reinterpret_cast<float4*>(s.bufB);

    // ---- layer 1 ----
    gemm<K1>(W1s, b1s, xsT4, bufA4, tid);
    gemm<K1>(W1d, b1d, xsT4, bufB4, tid);
    __syncthreads();
    gat_edge_phase(s, a1, tid);    // NOTE: destroys xsT (Amat alias)

    // ---- layer 2 ----
    gemm<K2>(W2s, b2s, hT4, bufA4, tid);
    gemm<K2>(W2d, b2d, hT4, bufB4, tid);
    __syncthreads();
    gat_edge_phase(s, a2, tid);    // overwrites hT/hN with h2

    // ---- global attention pooling ----
    if (tid < NV) {
        const float4* hN4 = reinterpret_cast<const float4*>(s.hN);
        const float4* wg4 = reinterpret_cast<const float4*>(Wg);
        float gacc = __ldg(&bg[0]);
#pragma unroll
        for (int q = 0; q < 16; q++) {
            const float4 hv = hN4[tid * HNS4 + q];
            const float4 w  = __ldg(&wg4[q]);
            gacc = fmaf(hv.x, w.x, gacc);
            gacc = fmaf(hv.y, w.y, gacc);
            gacc = fmaf(hv.z, w.z, gacc);
            gacc = fmaf(hv.w, w.w, gacc);
        }
        float m = gacc;
#pragma unroll
        for (int o = 16; o; o >>= 1) m = fmaxf(m, __shfl_xor_sync(0xffffffffu, m, o));
        const float ex = __expf(gacc - m);
        float d = ex;
#pragma unroll
        for (int o = 16; o; o >>= 1) d += __shfl_xor_sync(0xffffffffu, d, o);
        s.nalpha[tid] = ex / d;
    }
    __syncthreads();
    if (tid < DH) {
        float r = 0.f;
#pragma unroll
        for (int v = 0; v < NV; v++) r = fmaf(s.nalpha[v], s.hT[tid * STK + v], r);
        out[(size_t)g * DH + tid] = r;
    }
}

extern "C" void kernel_launch(void* const* d_in, const int* in_sizes, int n_in,
                              void* d_out, int out_size)
{
    const float* x   = (const float*)d_in[0];
    const int*   src = (const int*)d_in[1];
    const int*   dst = (const int*)d_in[2];
    const float* W1s = (const float*)d_in[4];
    const float* b1s = (const float*)d_in[5];
    const float* W1d = (const float*)d_in[6];
    const float* b1d = (const float*)d_in[7];
    const float* a1  = (const float*)d_in[8];
    const float* W2s = (const float*)d_in[9];
    const float* b2s = (const float*)d_in[10];
    const float* W2d = (const float*)d_in[11];
    const float* b2d = (const float*)d_in[12];
    const float* a2  = (const float*)d_in[13];
    const float* Wg  = (const float*)d_in[14];
    const float* bg  = (const float*)d_in[15];
    float* out = (float*)d_out;

    const int smem = (int)sizeof(Smem);
    cudaFuncSetAttribute(gat_fused_kernel,
                         cudaFuncAttributeMaxDynamicSharedMemorySize, smem);
    gat_fused_kernel<<<NGRAPHS, NT, smem>>>(x, src, dst,
                                            W1s, b1s, W1d, b1d, a1,
                                            W2s, b2s, W2d, b2d, a2,
                                            Wg, bg, out);
}

// round 7
// speedup vs baseline: 1.0223x; 1.0223x over previous
#include <cuda_runtime.h>

#define NV 32      // nodes per graph
#define NE 256     // edges per graph
#define NH 4       // heads
#define DH 64      // dim per head
#define CC 256     // NH*DH
#define K1 128     // layer-1 input dim
#define K2 64      // layer-2 input dim
#define NT 256     // threads per block
#define NGRAPHS 2048

#define SR4 65     // node-major row stride in float4 (65 ≡ 1 mod 32)
#define STK 36     // k-major stride (floats)
#define STK4 9
#define HNS4 17    // hN stride in float4
#define AMS 33     // Amat row stride in float4 (33 -> conflict-free across v)

struct __align__(16) Smem {
    float xsT[K1 * STK];    // x transposed [k][node]; reused as Amat
    float bufA[NV * SR4 * 4];   // hs, node-major [node][c]
    float bufB[NV * SR4 * 4];   // hd, node-major; overwritten by aggregation
    float hT[DH * STK];     // maxpooled h, k-major
    float hN[NV * HNS4 * 4];// maxpooled h, node-major
    float logits[NE * NH];
    float aw[CC];
    float mx[NV * NH];
    float den[NV * NH];
    float nalpha[NV];
    int esrc[NE];
    int edst[NE];
    int cnt[NV];
    int startv[NV + 1];
};

__device__ __forceinline__ void fma4(float4& acc, float s, const float4 w) {
    acc.x = fmaf(s, w.x, acc.x);
    acc.y = fmaf(s, w.y, acc.y);
    acc.z = fmaf(s, w.z, acc.z);
    acc.w = fmaf(s, w.w, acc.w);
}

// C[32, 256] = A[32, K] @ W[K, 256] + b, k-split across two thread groups.
// 256 threads = 2 k-groups (kg) x 2 row-groups (tr, 16 rows) x 64 col-groups (tc).
// Each W column stream is read by only 2 threads (was 8) -> W LDG wavefronts / 4.
// kg0 stores bias+partial; after barrier kg1 adds its partial in place.
template <int K>
__device__ __forceinline__ void gemm_ks(const float* __restrict__ W,
                                        const float* __restrict__ b,
                                        const float4* __restrict__ A4,
                                        float4* __restrict__ out4, int tid)
{
    const int kg = tid >> 7;        // 0/1 : k-half
    const int t  = tid & 127;
    const int tr = t >> 6;          // 0/1 : rows tr*16 .. tr*16+15
    const int tc = t & 63;          // cols tc*4 .. tc*4+3
    const float4* __restrict__ W4 = reinterpret_cast<const float4*>(W) + tc;

    float4 acc[16];
    if (kg == 0) {
        const float4 bias = __ldg(&reinterpret_cast<const float4*>(b)[tc]);
#pragma unroll
        for (int i = 0; i < 16; i++) acc[i] = bias;
    } else {
#pragma unroll
        for (int i = 0; i < 16; i++) acc[i] = make_float4(0.f, 0.f, 0.f, 0.f);
    }

    const int k0 = kg * (K / 2);
#pragma unroll 8
    for (int k = k0; k < k0 + K / 2; k++) {
        const float4 w  = __ldg(&W4[k * 64]);
        const float4 a0 = A4[k * STK4 + tr * 4 + 0];
        const float4 a1 = A4[k * STK4 + tr * 4 + 1];
        const float4 a2 = A4[k * STK4 + tr * 4 + 2];
        const float4 a3 = A4[k * STK4 + tr * 4 + 3];
        fma4(acc[0],  a0.x, w); fma4(acc[1],  a0.y, w);
        fma4(acc[2],  a0.z, w); fma4(acc[3],  a0.w, w);
        fma4(acc[4],  a1.x, w); fma4(acc[5],  a1.y, w);
        fma4(acc[6],  a1.z, w); fma4(acc[7],  a1.w, w);
        fma4(acc[8],  a2.x, w); fma4(acc[9],  a2.y, w);
        fma4(acc[10], a2.z, w); fma4(acc[11], a2.w, w);
        fma4(acc[12], a3.x, w); fma4(acc[13], a3.y, w);
        fma4(acc[14], a3.z, w); fma4(acc[15], a3.w, w);
    }

    if (kg == 0) {
#pragma unroll
        for (int i = 0; i < 16; i++) out4[(tr * 16 + i) * SR4 + tc] = acc[i];
    }
    __syncthreads();
    if (kg == 1) {
#pragma unroll
        for (int i = 0; i < 16; i++) {
            float4 o = out4[(tr * 16 + i) * SR4 + tc];
            o.x += acc[i].x; o.y += acc[i].y;
            o.z += acc[i].z; o.w += acc[i].w;
            out4[(tr * 16 + i) * SR4 + tc] = o;
        }
    }
}

// GATv2 edge phase. bufA = hs, bufB = hd (node-major). Agg overwrites bufB.
__device__ __forceinline__ void gat_edge_phase(Smem& s, const float* __restrict__ attn, int tid)
{
    s.aw[tid] = __ldg(&attn[tid]);
    __syncthreads();

    float4* bufA4 = reinterpret_cast<float4*>(s.bufA);
    float4* bufB4 = reinterpret_cast<float4*>(s.bufB);
    const float4* aw4 = reinterpret_cast<const float4*>(s.aw);
    float* Amat = s.xsT;                      // aliased: 32 x AMS float4
    float4* Amat4 = reinterpret_cast<float4*>(Amat);

    const int wid = tid >> 5, lane = tid & 31;
    const int eg = lane >> 3;                 // edge slot within warp (0..3)
    const int ln = lane & 7;                  // channel lane (0..7)

    float4 awr[8];
#pragma unroll
    for (int c = 0; c < 8; c++) awr[c] = aw4[c * 8 + ln];

    // --- logits: 4 edges per warp pass, 8 lanes per edge ---
#pragma unroll 2
    for (int pass = 0; pass < 8; pass++) {
        const int e = wid * 32 + pass * 4 + eg;
        const int ss = s.esrc[e], dd = s.edst[e];
        const float4* pa = bufA4 + ss * SR4;
        const float4* pb = bufB4 + dd * SR4;
        float part[NH] = {0.f, 0.f, 0.f, 0.f};
#pragma unroll
        for (int c = 0; c < 8; c++) {
            const float4 sa = pa[c * 8 + ln];
            const float4 sb = pb[c * 8 + ln];
            const float4 w  = awr[c];
            const int h = c >> 1;
            float v;
            v = sa.x + sb.x; part[h] = fmaf(w.x, v > 0.f ? v : 0.2f * v, part[h]);
            v = sa.y + sb.y; part[h] = fmaf(w.y, v > 0.f ? v : 0.2f * v, part[h]);
            v = sa.z + sb.z; part[h] = fmaf(w.z, v > 0.f ? v : 0.2f * v, part[h]);
            v = sa.w + sb.w; part[h] = fmaf(w.w, v > 0.f ? v : 0.2f * v, part[h]);
        }
#pragma unroll
        for (int o = 4; o; o >>= 1) {
            part[0] += __shfl_xor_sync(0xffffffffu, part[0], o);
            part[1] += __shfl_xor_sync(0xffffffffu, part[1], o);
            part[2] += __shfl_xor_sync(0xffffffffu, part[2], o);
            part[3] += __shfl_xor_sync(0xffffffffu, part[3], o);
        }
        if (ln == 0)
            *reinterpret_cast<float4*>(&s.logits[e * NH]) =
                make_float4(part[0], part[1], part[2], part[3]);
    }
    __syncthreads();

    // --- per (node, head) max & exp-sum; other half zeroes Amat ---
    if (tid < NV * NH) {
        const int v = tid >> 2, h = tid & 3;
        const int e0 = s.startv[v], e1 = s.startv[v + 1];
        float m = -1e30f;
        for (int j = e0; j < e1; j++) m = fmaxf(m, s.logits[j * NH + h]);
        float d = 0.f;
        for (int j = e0; j < e1; j++) d += __expf(s.logits[j * NH + h] - m);
        s.mx[tid]  = m;
        s.den[tid] = (d == 0.f) ? 1.f : d;
    } else {
        const float4 z = make_float4(0.f, 0.f, 0.f, 0.f);
        for (int i = tid - 128; i < NV * AMS; i += 128) Amat4[i] = z;
    }
    __syncthreads();

    // --- per-edge alpha -> dense Amat[dst][src] (float4 = 4 heads) ---
    {
        const int e = tid;
        const int dd = s.edst[e], ss = s.esrc[e];
        const float4 lg  = *reinterpret_cast<const float4*>(&s.logits[e * NH]);
        const float4 mxv = *reinterpret_cast<const float4*>(&s.mx[dd * NH]);
        const float4 dnv = *reinterpret_cast<const float4*>(&s.den[dd * NH]);
        float* am = Amat + (dd * AMS + ss) * 4;
        atomicAdd(am + 0, __expf(lg.x - mxv.x) / dnv.x);
        atomicAdd(am + 1, __expf(lg.y - mxv.y) / dnv.y);
        atomicAdd(am + 2, __expf(lg.z - mxv.z) / dnv.z);
        atomicAdd(am + 3, __expf(lg.w - mxv.w) / dnv.w);
    }
    __syncthreads();

    // --- dense aggregation: bufB[v] = sum_u Amat[v][u] (per head) * hs[u] ---
    {
        const int v = tid >> 3;
        const int l = tid & 7;
        float4 acc[8];
#pragma unroll
        for (int blk = 0; blk < 8; blk++) acc[blk] = make_float4(0.f, 0.f, 0.f, 0.f);
        const float4* AmV = Amat4 + v * AMS;
        for (int u = 0; u < NV; u++) {
            const float4 a4 = AmV[u];
            const bool nz = (a4.x != 0.f) | (a4.y != 0.f) | (a4.z != 0.f) | (a4.w != 0.f);
            if (!__any_sync(0xffffffffu, nz)) continue;
            const float4* p = bufA4 + u * SR4;
#pragma unroll
            for (int blk = 0; blk < 8; blk++) {
                const int h = blk >> 1;
                const float a = (h == 0) ? a4.x : (h == 1) ? a4.y : (h == 2) ? a4.z : a4.w;
                fma4(acc[blk], a, p[blk * 8 + l]);
            }
        }
#pragma unroll
        for (int blk = 0; blk < 8; blk++) bufB4[v * SR4 + blk * 8 + l] = acc[blk];
    }
    __syncthreads();

    // --- head maxpool -> hT[k][v] and hN[v][k] ---
    float4* hN4 = reinterpret_cast<float4*>(s.hN);
    for (int i = tid; i < NV * DH / 4; i += NT) {
        const int v = i >> 4, q = i & 15;
        float4 m = bufB4[v * SR4 + q];
#pragma unroll
        for (int h = 1; h < NH; h++) {
            const float4 t = bufB4[v * SR4 + h * 16 + q];
            m.x = fmaxf(m.x, t.x); m.y = fmaxf(m.y, t.y);
            m.z = fmaxf(m.z, t.z); m.w = fmaxf(m.w, t.w);
        }
        hN4[v * HNS4 + q] = m;
        const int k0 = q * 4;
        s.hT[(k0 + 0) * STK + v] = m.x;
        s.hT[(k0 + 1) * STK + v] = m.y;
        s.hT[(k0 + 2) * STK + v] = m.z;
        s.hT[(k0 + 3) * STK + v] = m.w;
    }
    __syncthreads();
}

__global__ __launch_bounds__(NT, 2)
void gat_fused_kernel(const float* __restrict__ x,
                      const int* __restrict__ src,
                      const int* __restrict__ dst,
                      const float* __restrict__ W1s, const float* __restrict__ b1s,
                      const float* __restrict__ W1d, const float* __restrict__ b1d,
                      const float* __restrict__ a1,
                      const float* __restrict__ W2s, const float* __restrict__ b2s,
                      const float* __restrict__ W2d, const float* __restrict__ b2d,
                      const float* __restrict__ a2,
                      const float* __restrict__ Wg, const float* __restrict__ bg,
                      float* __restrict__ out)
{
    extern __shared__ unsigned char smraw[];
    Smem& s = *reinterpret_cast<Smem*>(smraw);
    const int g = blockIdx.x, tid = threadIdx.x;

    // ---- phase 0: load x transposed, count-sort edges by dst ----
    {
        const float* xg = x + (size_t)g * NV * K1;
        for (int i = tid; i < NV * K1; i += NT) {
            const int row = i >> 7, k = i & 127;
            s.xsT[k * STK + row] = __ldg(&xg[i]);
        }
        const int rs = src[g * NE + tid] - g * NV;
        const int rd = dst[g * NE + tid] - g * NV;
        if (tid < NV) s.cnt[tid] = 0;
        __syncthreads();
        const int p = atomicAdd(&s.cnt[rd], 1);
        __syncthreads();
        if (tid == 0) {
            int acc = 0;
            for (int v = 0; v < NV; v++) { s.startv[v] = acc; acc += s.cnt[v]; }
            s.startv[NV] = acc;
        }
        __syncthreads();
        const int j = s.startv[rd] + p;
        s.esrc[j] = rs;
        s.edst[j] = rd;
    }
    __syncthreads();

    float4* xsT4  = reinterpret_cast<float4*>(s.xsT);
    float4* hT4   = reinterpret_cast<float4*>(s.hT);
    float4* bufA4 = reinterpret_cast<float4*>(s.bufA);
    float4* bufB4 = reinterpret_cast<float4*>(s.bufB);

    // ---- layer 1 ----
    gemm_ks<K1>(W1s, b1s, xsT4, bufA4, tid);
    __syncthreads();
    gemm_ks<K1>(W1d, b1d, xsT4, bufB4, tid);
    __syncthreads();
    gat_edge_phase(s, a1, tid);    // NOTE: destroys xsT (Amat alias)

    // ---- layer 2 ----
    gemm_ks<K2>(W2s, b2s, hT4, bufA4, tid);
    __syncthreads();
    gemm_ks<K2>(W2d, b2d, hT4, bufB4, tid);
    __syncthreads();
    gat_edge_phase(s, a2, tid);    // overwrites hT/hN with h2

    // ---- global attention pooling ----
    if (tid < NV) {
        const float4* hN4 = reinterpret_cast<const float4*>(s.hN);
        const float4* wg4 = reinterpret_cast<const float4*>(Wg);
        float gacc = __ldg(&bg[0]);
#pragma unroll
        for (int q = 0; q < 16; q++) {
            const float4 hv = hN4[tid * HNS4 + q];
            const float4 w  = __ldg(&wg4[q]);
            gacc = fmaf(hv.x, w.x, gacc);
            gacc = fmaf(hv.y, w.y, gacc);
            gacc = fmaf(hv.z, w.z, gacc);
            gacc = fmaf(hv.w, w.w, gacc);
        }
        float m = gacc;
#pragma unroll
        for (int o = 16; o; o >>= 1) m = fmaxf(m, __shfl_xor_sync(0xffffffffu, m, o));
        const float ex = __expf(gacc - m);
        float d = ex;
#pragma unroll
        for (int o = 16; o; o >>= 1) d += __shfl_xor_sync(0xffffffffu, d, o);
        s.nalpha[tid] = ex / d;
    }
    __syncthreads();
    if (tid < DH) {
        float r = 0.f;
#pragma unroll
        for (int v = 0; v < NV; v++) r = fmaf(s.nalpha[v], s.hT[tid * STK + v], r);
        out[(size_t)g * DH + tid] = r;
    }
}

extern "C" void kernel_launch(void* const* d_in, const int* in_sizes, int n_in,
                              void* d_out, int out_size)
{
    const float* x   = (const float*)d_in[0];
    const int*   src = (const int*)d_in[1];
    const int*   dst = (const int*)d_in[2];
    const float* W1s = (const float*)d_in[4];
    const float* b1s = (const float*)d_in[5];
    const float* W1d = (const float*)d_in[6];
    const float* b1d = (const float*)d_in[7];
    const float* a1  = (const float*)d_in[8];
    const float* W2s = (const float*)d_in[9];
    const float* b2s = (const float*)d_in[10];
    const float* W2d = (const float*)d_in[11];
    const float* b2d = (const float*)d_in[12];
    const float* a2  = (const float*)d_in[13];
    const float* Wg  = (const float*)d_in[14];
    const float* bg  = (const float*)d_in[15];
    float* out = (float*)d_out;

    const int smem = (int)sizeof(Smem);
    cudaFuncSetAttribute(gat_fused_kernel,
                         cudaFuncAttributeMaxDynamicSharedMemorySize, smem);
    gat_fused_kernel<<<NGRAPHS, NT, smem>>>(x, src, dst,
                                            W1s, b1s, W1d, b1d, a1,
                                            W2s, b2s, W2d, b2d, a2,
                                            Wg, bg, out);
}

// round 10
// speedup vs baseline: 1.0913x; 1.0675x over previous
#include <cuda_runtime.h>

#define NV 32      // nodes per graph
#define NE 256     // edges per graph
#define NH 4       // heads
#define DH 64      // dim per head
#define CC 256     // NH*DH
#define K1 128     // layer-1 input dim
#define K2 64      // layer-2 input dim
#define NT 256     // threads per block
#define NGRAPHS 2048

#define SR4 65     // node-major row stride in float4 (65 ≡ 1 mod 32)
#define STK 36     // k-major stride (floats)
#define STK4 9
#define HNS4 17    // hN stride in float4
#define AMS 33     // Amat row stride in float4 (33 -> conflict-free across v)

struct __align__(16) Smem {
    float xsT[K1 * STK];    // x transposed [k][node]; reused as Amat
    float bufA[NV * SR4 * 4];   // hs, node-major [node][c]
    float bufB[NV * SR4 * 4];   // hd, node-major; overwritten by aggregation
    float hT[DH * STK];     // maxpooled h, k-major
    float hN[NV * HNS4 * 4];// maxpooled h, node-major
    float logits[NE * NH];
    float aw[CC];
    float mx[NV * NH];
    float den[NV * NH];
    float nalpha[NV];
    int esrc[NE];
    int edst[NE];
    int cnt[NV];
    int startv[NV + 1];
};

__device__ __forceinline__ void fma4(float4& acc, float s, const float4 w) {
    acc.x = fmaf(s, w.x, acc.x);
    acc.y = fmaf(s, w.y, acc.y);
    acc.z = fmaf(s, w.z, acc.z);
    acc.w = fmaf(s, w.w, acc.w);
}

// C[32, 256] = A[32, K] @ W[K, 256] + b, warp-internal k-parity split.
// Warp w owns 8 float4 cols (w*8..w*8+7), all 32 rows, full K.
// Lane = kg (k parity) x tr (16-row group) x tc (col). Each W 128B chunk is
// read by exactly one 16-lane half once -> W LDG wavefronts minimal (read-once).
// kg halves are combined by 64 SHFL.BFLY(16) + FADD in registers: NO smem epilogue.
// Parity split (even/odd k) keeps the 4 A-LDS per step on 4 distinct bank groups.
template <int K>
__device__ __forceinline__ void gemm_ws(const float* __restrict__ W,
                                        const float* __restrict__ b,
                                        const float4* __restrict__ A4,
                                        float4* __restrict__ out4, int tid)
{
    const int w    = tid >> 5;          // warp -> float4 cols w*8 .. w*8+7
    const int lane = tid & 31;
    const int kg   = lane >> 4;         // 0: even k, 1: odd k
    const int tr   = (lane >> 3) & 1;   // 16-row group
    const int tc   = lane & 7;          // float4 col within warp
    const int col  = w * 8 + tc;
    const float4* __restrict__ W4 = reinterpret_cast<const float4*>(W) + col;

    float4 acc[16];
#pragma unroll
    for (int i = 0; i < 16; i++) acc[i] = make_float4(0.f, 0.f, 0.f, 0.f);

#pragma unroll 4
    for (int i = 0; i < K / 2; i++) {
        const int k = 2 * i + kg;
        const float4 wv = __ldg(&W4[k * 64]);
        const float4 a0 = A4[k * STK4 + tr * 4 + 0];
        const float4 a1 = A4[k * STK4 + tr * 4 + 1];
        const float4 a2 = A4[k * STK4 + tr * 4 + 2];
        const float4 a3 = A4[k * STK4 + tr * 4 + 3];
        fma4(acc[0],  a0.x, wv); fma4(acc[1],  a0.y, wv);
        fma4(acc[2],  a0.z, wv); fma4(acc[3],  a0.w, wv);
        fma4(acc[4],  a1.x, wv); fma4(acc[5],  a1.y, wv);
        fma4(acc[6],  a1.z, wv); fma4(acc[7],  a1.w, wv);
        fma4(acc[8],  a2.x, wv); fma4(acc[9],  a2.y, wv);
        fma4(acc[10], a2.z, wv); fma4(acc[11], a2.w, wv);
        fma4(acc[12], a3.x, wv); fma4(acc[13], a3.y, wv);
        fma4(acc[14], a3.z, wv); fma4(acc[15], a3.w, wv);
    }

    // combine even/odd k halves across the lane^16 pair (register-only)
#pragma unroll
    for (int i = 0; i < 16; i++) {
        acc[i].x += __shfl_xor_sync(0xffffffffu, acc[i].x, 16);
        acc[i].y += __shfl_xor_sync(0xffffffffu, acc[i].y, 16);
        acc[i].z += __shfl_xor_sync(0xffffffffu, acc[i].z, 16);
        acc[i].w += __shfl_xor_sync(0xffffffffu, acc[i].w, 16);
    }

    if (kg == 0) {
        const float4 bias = __ldg(&reinterpret_cast<const float4*>(b)[col]);
#pragma unroll
        for (int i = 0; i < 16; i++) {
            float4 o = acc[i];
            o.x += bias.x; o.y += bias.y; o.z += bias.z; o.w += bias.w;
            out4[(tr * 16 + i) * SR4 + col] = o;
        }
    }
}

// GATv2 edge phase. bufA = hs, bufB = hd (node-major). Agg overwrites bufB.
__device__ __forceinline__ void gat_edge_phase(Smem& s, const float* __restrict__ attn, int tid)
{
    s.aw[tid] = __ldg(&attn[tid]);
    __syncthreads();

    float4* bufA4 = reinterpret_cast<float4*>(s.bufA);
    float4* bufB4 = reinterpret_cast<float4*>(s.bufB);
    const float4* aw4 = reinterpret_cast<const float4*>(s.aw);
    float* Amat = s.xsT;                      // aliased: 32 x AMS float4
    float4* Amat4 = reinterpret_cast<float4*>(Amat);

    const int wid = tid >> 5, lane = tid & 31;
    const int eg = lane >> 3;                 // edge slot within warp (0..3)
    const int ln = lane & 7;                  // channel lane (0..7)

    float4 awr[8];
#pragma unroll
    for (int c = 0; c < 8; c++) awr[c] = aw4[c * 8 + ln];

    // --- logits: 4 edges per warp pass, 8 lanes per edge ---
#pragma unroll 2
    for (int pass = 0; pass < 8; pass++) {
        const int e = wid * 32 + pass * 4 + eg;
        const int ss = s.esrc[e], dd = s.edst[e];
        const float4* pa = bufA4 + ss * SR4;
        const float4* pb = bufB4 + dd * SR4;
        float part[NH] = {0.f, 0.f, 0.f, 0.f};
#pragma unroll
        for (int c = 0; c < 8; c++) {
            const float4 sa = pa[c * 8 + ln];
            const float4 sb = pb[c * 8 + ln];
            const float4 w  = awr[c];
            const int h = c >> 1;
            float v;
            v = sa.x + sb.x; part[h] = fmaf(w.x, v > 0.f ? v : 0.2f * v, part[h]);
            v = sa.y + sb.y; part[h] = fmaf(w.y, v > 0.f ? v : 0.2f * v, part[h]);
            v = sa.z + sb.z; part[h] = fmaf(w.z, v > 0.f ? v : 0.2f * v, part[h]);
            v = sa.w + sb.w; part[h] = fmaf(w.w, v > 0.f ? v : 0.2f * v, part[h]);
        }
#pragma unroll
        for (int o = 4; o; o >>= 1) {
            part[0] += __shfl_xor_sync(0xffffffffu, part[0], o);
            part[1] += __shfl_xor_sync(0xffffffffu, part[1], o);
            part[2] += __shfl_xor_sync(0xffffffffu, part[2], o);
            part[3] += __shfl_xor_sync(0xffffffffu, part[3], o);
        }
        if (ln == 0)
            *reinterpret_cast<float4*>(&s.logits[e * NH]) =
                make_float4(part[0], part[1], part[2], part[3]);
    }
    __syncthreads();

    // --- per (node, head) max & exp-sum; other half zeroes Amat ---
    if (tid < NV * NH) {
        const int v = tid >> 2, h = tid & 3;
        const int e0 = s.startv[v], e1 = s.startv[v + 1];
        float m = -1e30f;
        for (int j = e0; j < e1; j++) m = fmaxf(m, s.logits[j * NH + h]);
        float d = 0.f;
        for (int j = e0; j < e1; j++) d += __expf(s.logits[j * NH + h] - m);
        s.mx[tid]  = m;
        s.den[tid] = (d == 0.f) ? 1.f : d;
    } else {
        const float4 z = make_float4(0.f, 0.f, 0.f, 0.f);
        for (int i = tid - 128; i < NV * AMS; i += 128) Amat4[i] = z;
    }
    __syncthreads();

    // --- per-edge alpha -> dense Amat[dst][src] (float4 = 4 heads) ---
    {
        const int e = tid;
        const int dd = s.edst[e], ss = s.esrc[e];
        const float4 lg  = *reinterpret_cast<const float4*>(&s.logits[e * NH]);
        const float4 mxv = *reinterpret_cast<const float4*>(&s.mx[dd * NH]);
        const float4 dnv = *reinterpret_cast<const float4*>(&s.den[dd * NH]);
        float* am = Amat + (dd * AMS + ss) * 4;
        atomicAdd(am + 0, __expf(lg.x - mxv.x) / dnv.x);
        atomicAdd(am + 1, __expf(lg.y - mxv.y) / dnv.y);
        atomicAdd(am + 2, __expf(lg.z - mxv.z) / dnv.z);
        atomicAdd(am + 3, __expf(lg.w - mxv.w) / dnv.w);
    }
    __syncthreads();

    // --- dense aggregation: bufB[v] = sum_u Amat[v][u] (per head) * hs[u] ---
    {
        const int v = tid >> 3;
        const int l = tid & 7;
        float4 acc[8];
#pragma unroll
        for (int blk = 0; blk < 8; blk++) acc[blk] = make_float4(0.f, 0.f, 0.f, 0.f);
        const float4* AmV = Amat4 + v * AMS;
        for (int u = 0; u < NV; u++) {
            const float4 a4 = AmV[u];
            const bool nz = (a4.x != 0.f) | (a4.y != 0.f) | (a4.z != 0.f) | (a4.w != 0.f);
            if (!__any_sync(0xffffffffu, nz)) continue;
            const float4* p = bufA4 + u * SR4;
#pragma unroll
            for (int blk = 0; blk < 8; blk++) {
                const int h = blk >> 1;
                const float a = (h == 0) ? a4.x : (h == 1) ? a4.y : (h == 2) ? a4.z : a4.w;
                fma4(acc[blk], a, p[blk * 8 + l]);
            }
        }
#pragma unroll
        for (int blk = 0; blk < 8; blk++) bufB4[v * SR4 + blk * 8 + l] = acc[blk];
    }
    __syncthreads();

    // --- head maxpool -> hT[k][v] and hN[v][k] ---
    float4* hN4 = reinterpret_cast<float4*>(s.hN);
    for (int i = tid; i < NV * DH / 4; i += NT) {
        const int v = i >> 4, q = i & 15;
        float4 m = bufB4[v * SR4 + q];
#pragma unroll
        for (int h = 1; h < NH; h++) {
            const float4 t = bufB4[v * SR4 + h * 16 + q];
            m.x = fmaxf(m.x, t.x); m.y = fmaxf(m.y, t.y);
            m.z = fmaxf(m.z, t.z); m.w = fmaxf(m.w, t.w);
        }
        hN4[v * HNS4 + q] = m;
        const int k0 = q * 4;
        s.hT[(k0 + 0) * STK + v] = m.x;
        s.hT[(k0 + 1) * STK + v] = m.y;
        s.hT[(k0 + 2) * STK + v] = m.z;
        s.hT[(k0 + 3) * STK + v] = m.w;
    }
    __syncthreads();
}

__global__ __launch_bounds__(NT, 2)
void gat_fused_kernel(const float* __restrict__ x,
                      const int* __restrict__ src,
                      const int* __restrict__ dst,
                      const float* __restrict__ W1s, const float* __restrict__ b1s,
                      const float* __restrict__ W1d, const float* __restrict__ b1d,
                      const float* __restrict__ a1,
                      const float* __restrict__ W2s, const float* __restrict__ b2s,
                      const float* __restrict__ W2d, const float* __restrict__ b2d,
                      const float* __restrict__ a2,
                      const float* __restrict__ Wg, const float* __restrict__ bg,
                      float* __restrict__ out)
{
    extern __shared__ unsigned char smraw[];
    Smem& s = *reinterpret_cast<Smem*>(smraw);
    const int g = blockIdx.x, tid = threadIdx.x;

    // ---- phase 0: load x transposed, count-sort edges by dst ----
    {
        const float* xg = x + (size_t)g * NV * K1;
        for (int i = tid; i < NV * K1; i += NT) {
            const int row = i >> 7, k = i & 127;
            s.xsT[k * STK + row] = __ldg(&xg[i]);
        }
        const int rs = src[g * NE + tid] - g * NV;
        const int rd = dst[g * NE + tid] - g * NV;
        if (tid < NV) s.cnt[tid] = 0;
        __syncthreads();
        const int p = atomicAdd(&s.cnt[rd], 1);
        __syncthreads();
        if (tid == 0) {
            int acc = 0;
            for (int v = 0; v < NV; v++) { s.startv[v] = acc; acc += s.cnt[v]; }
            s.startv[NV] = acc;
        }
        __syncthreads();
        const int j = s.startv[rd] + p;
        s.esrc[j] = rs;
        s.edst[j] = rd;
    }
    __syncthreads();

    float4* xsT4  = reinterpret_cast<float4*>(s.xsT);
    float4* hT4   = reinterpret_cast<float4*>(s.hT);
    float4* bufA4 = reinterpret_cast<float4*>(s.bufA);
    float4* bufB4 = reinterpret_cast<float4*>(s.bufB);

    // ---- layer 1 ----
    gemm_ws<K1>(W1s, b1s, xsT4, bufA4, tid);
    gemm_ws<K1>(W1d, b1d, xsT4, bufB4, tid);
    __syncthreads();
    gat_edge_phase(s, a1, tid);    // NOTE: destroys xsT (Amat alias)

    // ---- layer 2 ----
    gemm_ws<K2>(W2s, b2s, hT4, bufA4, tid);
    gemm_ws<K2>(W2d, b2d, hT4, bufB4, tid);
    __syncthreads();
    gat_edge_phase(s, a2, tid);    // overwrites hT/hN with h2

    // ---- global attention pooling ----
    if (tid < NV) {
        const float4* hN4 = reinterpret_cast<const float4*>(s.hN);
        const float4* wg4 = reinterpret_cast<const float4*>(Wg);
        float gacc = __ldg(&bg[0]);
#pragma unroll
        for (int q = 0; q < 16; q++) {
            const float4 hv = hN4[tid * HNS4 + q];
            const float4 w  = __ldg(&wg4[q]);
            gacc = fmaf(hv.x, w.x, gacc);
            gacc = fmaf(hv.y, w.y, gacc);
            gacc = fmaf(hv.z, w.z, gacc);
            gacc = fmaf(hv.w, w.w, gacc);
        }
        float m = gacc;
#pragma unroll
        for (int o = 16; o; o >>= 1) m = fmaxf(m, __shfl_xor_sync(0xffffffffu, m, o));
        const float ex = __expf(gacc - m);
        float d = ex;
#pragma unroll
        for (int o = 16; o; o >>= 1) d += __shfl_xor_sync(0xffffffffu, d, o);
        s.nalpha[tid] = ex / d;
    }
    __syncthreads();
    if (tid < DH) {
        float r = 0.f;
#pragma unroll
        for (int v = 0; v < NV; v++) r = fmaf(s.nalpha[v], s.hT[tid * STK + v], r);
        out[(size_t)g * DH + tid] = r;
    }
}

extern "C" void kernel_launch(void* const* d_in, const int* in_sizes, int n_in,
                              void* d_out, int out_size)
{
    const float* x   = (const float*)d_in[0];
    const int*   src = (const int*)d_in[1];
    const int*   dst = (const int*)d_in[2];
    const float* W1s = (const float*)d_in[4];
    const float* b1s = (const float*)d_in[5];
    const float* W1d = (const float*)d_in[6];
    const float* b1d = (const float*)d_in[7];
    const float* a1  = (const float*)d_in[8];
    const float* W2s = (const float*)d_in[9];
    const float* b2s = (const float*)d_in[10];
    const float* W2d = (const float*)d_in[11];
    const float* b2d = (const float*)d_in[12];
    const float* a2  = (const float*)d_in[13];
    const float* Wg  = (const float*)d_in[14];
    const float* bg  = (const float*)d_in[15];
    float* out = (float*)d_out;

    const int smem = (int)sizeof(Smem);
    cudaFuncSetAttribute(gat_fused_kernel,
                         cudaFuncAttributeMaxDynamicSharedMemorySize, smem);
    gat_fused_kernel<<<NGRAPHS, NT, smem>>>(x, src, dst,
                                            W1s, b1s, W1d, b1d, a1,
                                            W2s, b2s, W2d, b2d, a2,
                                            Wg, bg, out);
}

// round 11
// speedup vs baseline: 1.5354x; 1.4070x over previous
#include <cuda_runtime.h>
#include <cstdint>

#define NV 32      // nodes per graph
#define NE 256     // edges per graph
#define NH 4       // heads
#define DH 64      // dim per head
#define CC 256     // NH*DH
#define K1 128     // layer-1 input dim
#define K2 64      // layer-2 input dim
#define NT 256     // threads per block
#define NGRAPHS 2048

#define SR4 65     // node-major row stride in float4 (65 ≡ 1 mod 32)
#define SRF 260    // node-major row stride in floats
#define STK 36     // k-major stride (floats)
#define STK4 9
#define HNS4 17    // hN stride in float4
#define AMS 33     // Amat row stride in float4

// ---- tf32 fragment scratch for the 4 projection weights ----
// Layout per W: [kstep][n8tile][lane][2] floats (pre-cvt.rna tf32 bit patterns).
// K1 W: 16*32*32*2 = 32768 floats. K2 W: 8*32*32*2 = 16384 floats.
#define WF_W1S 0
#define WF_W1D 32768
#define WF_W2S 65536
#define WF_W2D 81920
__device__ float g_wf[98304];

__global__ void prep_w_kernel(const float* __restrict__ W1s, const float* __restrict__ W1d,
                              const float* __restrict__ W2s, const float* __restrict__ W2d)
{
    const int i = blockIdx.x * blockDim.x + threadIdx.x;
    if (i >= 49152) return;
    const float* W; int base, idx;
    if (i < 16384)      { W = W1s; base = WF_W1S; idx = i; }
    else if (i < 32768) { W = W1d; base = WF_W1D; idx = i - 16384; }
    else if (i < 40960) { W = W2s; base = WF_W2S; idx = i - 32768; }
    else                { W = W2d; base = WF_W2D; idx = i - 40960; }
    const int t   = idx >> 10;          // kstep
    const int rem = idx & 1023;
    const int n8  = rem >> 5;           // n-tile
    const int l   = rem & 31;           // lane
    const int k0  = t * 8 + (l & 3);
    const int n   = n8 * 8 + (l >> 2);
    const float v0 = W[k0 * 256 + n];
    const float v1 = W[(k0 + 4) * 256 + n];
    uint32_t r0, r1;
    asm("cvt.rna.tf32.f32 %0, %1;" : "=r"(r0) : "f"(v0));
    asm("cvt.rna.tf32.f32 %0, %1;" : "=r"(r1) : "f"(v1));
    g_wf[base + idx * 2 + 0] = __uint_as_float(r0);
    g_wf[base + idx * 2 + 1] = __uint_as_float(r1);
}

struct __align__(16) Smem {
    float xsT[K1 * STK];    // x transposed [k][node]; reused as Amat
    float bufA[NV * SRF];   // hs, node-major [node][c]
    float bufB[NV * SRF];   // hd, node-major; overwritten by aggregation
    float hT[DH * STK];     // maxpooled h, k-major
    float hN[NV * HNS4 * 4];// maxpooled h, node-major
    float logits[NE * NH];
    float aw[CC];
    float mx[NV * NH];
    float den[NV * NH];
    float nalpha[NV];
    int esrc[NE];
    int edst[NE];
    int cnt[NV];
    int startv[NV + 1];
};

__device__ __forceinline__ void fma4(float4& acc, float s, const float4 w) {
    acc.x = fmaf(s, w.x, acc.x);
    acc.y = fmaf(s, w.y, acc.y);
    acc.z = fmaf(s, w.z, acc.z);
    acc.w = fmaf(s, w.w, acc.w);
}

// C[32,256] = A[32,K] @ W[K,256] + b via tf32 mma.sync m16n8k8.
// Warp w: m-group mg = w&1 (16 rows), n-tiles n8 = (w>>1)*8 .. +7.
// A from k-major smem (stride STK) with cvt.rna; B from pre-swizzled g_wf
// (one coalesced LDG.64 per tile per kstep); C stored node-major (stride SRF).
template <int T>   // T = K/8 ksteps
__device__ __forceinline__ void gemm_mma(const float* __restrict__ Wf,
                                         const float* __restrict__ bias,
                                         const float* __restrict__ As,
                                         float* __restrict__ outb, int tid)
{
    const int w = tid >> 5, lane = tid & 31;
    const int mg = w & 1;
    const int n8b = (w >> 1) * 8;
    const int tg  = lane & 3;    // thread-in-group
    const int gid = lane >> 2;   // group id
    const int arow = mg * 16 + gid;

    float acc[8][4];
#pragma unroll
    for (int i = 0; i < 8; i++) {
        const int col = (n8b + i) * 8 + tg * 2;
        const float b0 = __ldg(&bias[col]);
        const float b1 = __ldg(&bias[col + 1]);
        acc[i][0] = b0; acc[i][1] = b1; acc[i][2] = b0; acc[i][3] = b1;
    }

#pragma unroll
    for (int t = 0; t < T; t++) {
        const float f0 = As[(t * 8 + tg) * STK + arow];
        const float f1 = As[(t * 8 + tg) * STK + arow + 8];
        const float f2 = As[(t * 8 + tg + 4) * STK + arow];
        const float f3 = As[(t * 8 + tg + 4) * STK + arow + 8];
        uint32_t a0, a1, a2, a3;
        asm("cvt.rna.tf32.f32 %0, %1;" : "=r"(a0) : "f"(f0));
        asm("cvt.rna.tf32.f32 %0, %1;" : "=r"(a1) : "f"(f1));
        asm("cvt.rna.tf32.f32 %0, %1;" : "=r"(a2) : "f"(f2));
        asm("cvt.rna.tf32.f32 %0, %1;" : "=r"(a3) : "f"(f3));
        const float2* bf = reinterpret_cast<const float2*>(Wf) + ((t * 32 + n8b) * 32 + lane);
#pragma unroll
        for (int i = 0; i < 8; i++) {
            const float2 bv = __ldg(&bf[i * 32]);
            const uint32_t b0 = __float_as_uint(bv.x);
            const uint32_t b1 = __float_as_uint(bv.y);
            asm volatile(
                "mma.sync.aligned.m16n8k8.row.col.f32.tf32.tf32.f32 "
                "{%0,%1,%2,%3}, {%4,%5,%6,%7}, {%8,%9}, {%0,%1,%2,%3};"
                : "+f"(acc[i][0]), "+f"(acc[i][1]), "+f"(acc[i][2]), "+f"(acc[i][3])
                : "r"(a0), "r"(a1), "r"(a2), "r"(a3), "r"(b0), "r"(b1));
        }
    }

#pragma unroll
    for (int i = 0; i < 8; i++) {
        const int col = (n8b + i) * 8 + tg * 2;
        *reinterpret_cast<float2*>(&outb[(mg * 16 + gid) * SRF + col]) =
            make_float2(acc[i][0], acc[i][1]);
        *reinterpret_cast<float2*>(&outb[(mg * 16 + gid + 8) * SRF + col]) =
            make_float2(acc[i][2], acc[i][3]);
    }
}

// GATv2 edge phase. bufA = hs, bufB = hd (node-major). Agg overwrites bufB.
__device__ __forceinline__ void gat_edge_phase(Smem& s, const float* __restrict__ attn, int tid)
{
    s.aw[tid] = __ldg(&attn[tid]);
    __syncthreads();

    float4* bufA4 = reinterpret_cast<float4*>(s.bufA);
    float4* bufB4 = reinterpret_cast<float4*>(s.bufB);
    const float4* aw4 = reinterpret_cast<const float4*>(s.aw);
    float* Amat = s.xsT;
    float4* Amat4 = reinterpret_cast<float4*>(Amat);

    const int wid = tid >> 5, lane = tid & 31;
    const int eg = lane >> 3;
    const int ln = lane & 7;

    float4 awr[8];
#pragma unroll
    for (int c = 0; c < 8; c++) awr[c] = aw4[c * 8 + ln];

#pragma unroll 2
    for (int pass = 0; pass < 8; pass++) {
        const int e = wid * 32 + pass * 4 + eg;
        const int ss = s.esrc[e], dd = s.edst[e];
        const float4* pa = bufA4 + ss * SR4;
        const float4* pb = bufB4 + dd * SR4;
        float part[NH] = {0.f, 0.f, 0.f, 0.f};
#pragma unroll
        for (int c = 0; c < 8; c++) {
            const float4 sa = pa[c * 8 + ln];
            const float4 sb = pb[c * 8 + ln];
            const float4 w  = awr[c];
            const int h = c >> 1;
            float v;
            v = sa.x + sb.x; part[h] = fmaf(w.x, v > 0.f ? v : 0.2f * v, part[h]);
            v = sa.y + sb.y; part[h] = fmaf(w.y, v > 0.f ? v : 0.2f * v, part[h]);
            v = sa.z + sb.z; part[h] = fmaf(w.z, v > 0.f ? v : 0.2f * v, part[h]);
            v = sa.w + sb.w; part[h] = fmaf(w.w, v > 0.f ? v : 0.2f * v, part[h]);
        }
#pragma unroll
        for (int o = 4; o; o >>= 1) {
            part[0] += __shfl_xor_sync(0xffffffffu, part[0], o);
            part[1] += __shfl_xor_sync(0xffffffffu, part[1], o);
            part[2] += __shfl_xor_sync(0xffffffffu, part[2], o);
            part[3] += __shfl_xor_sync(0xffffffffu, part[3], o);
        }
        if (ln == 0)
            *reinterpret_cast<float4*>(&s.logits[e * NH]) =
                make_float4(part[0], part[1], part[2], part[3]);
    }
    __syncthreads();

    if (tid < NV * NH) {
        const int v = tid >> 2, h = tid & 3;
        const int e0 = s.startv[v], e1 = s.startv[v + 1];
        float m = -1e30f;
        for (int j = e0; j < e1; j++) m = fmaxf(m, s.logits[j * NH + h]);
        float d = 0.f;
        for (int j = e0; j < e1; j++) d += __expf(s.logits[j * NH + h] - m);
        s.mx[tid]  = m;
        s.den[tid] = (d == 0.f) ? 1.f : d;
    } else {
        const float4 z = make_float4(0.f, 0.f, 0.f, 0.f);
        for (int i = tid - 128; i < NV * AMS; i += 128) Amat4[i] = z;
    }
    __syncthreads();

    {
        const int e = tid;
        const int dd = s.edst[e], ss = s.esrc[e];
        const float4 lg  = *reinterpret_cast<const float4*>(&s.logits[e * NH]);
        const float4 mxv = *reinterpret_cast<const float4*>(&s.mx[dd * NH]);
        const float4 dnv = *reinterpret_cast<const float4*>(&s.den[dd * NH]);
        float* am = Amat + (dd * AMS + ss) * 4;
        atomicAdd(am + 0, __expf(lg.x - mxv.x) / dnv.x);
        atomicAdd(am + 1, __expf(lg.y - mxv.y) / dnv.y);
        atomicAdd(am + 2, __expf(lg.z - mxv.z) / dnv.z);
        atomicAdd(am + 3, __expf(lg.w - mxv.w) / dnv.w);
    }
    __syncthreads();

    {
        const int v = tid >> 3;
        const int l = tid & 7;
        float4 acc[8];
#pragma unroll
        for (int blk = 0; blk < 8; blk++) acc[blk] = make_float4(0.f, 0.f, 0.f, 0.f);
        const float4* AmV = Amat4 + v * AMS;
        for (int u = 0; u < NV; u++) {
            const float4 a4 = AmV[u];
            const bool nz = (a4.x != 0.f) | (a4.y != 0.f) | (a4.z != 0.f) | (a4.w != 0.f);
            if (!__any_sync(0xffffffffu, nz)) continue;
            const float4* p = bufA4 + u * SR4;
#pragma unroll
            for (int blk = 0; blk < 8; blk++) {
                const int h = blk >> 1;
                const float a = (h == 0) ? a4.x : (h == 1) ? a4.y : (h == 2) ? a4.z : a4.w;
                fma4(acc[blk], a, p[blk * 8 + l]);
            }
        }
#pragma unroll
        for (int blk = 0; blk < 8; blk++) bufB4[v * SR4 + blk * 8 + l] = acc[blk];
    }
    __syncthreads();

    float4* hN4 = reinterpret_cast<float4*>(s.hN);
    for (int i = tid; i < NV * DH / 4; i += NT) {
        const int v = i >> 4, q = i & 15;
        float4 m = bufB4[v * SR4 + q];
#pragma unroll
        for (int h = 1; h < NH; h++) {
            const float4 t = bufB4[v * SR4 + h * 16 + q];
            m.x = fmaxf(m.x, t.x); m.y = fmaxf(m.y, t.y);
            m.z = fmaxf(m.z, t.z); m.w = fmaxf(m.w, t.w);
        }
        hN4[v * HNS4 + q] = m;
        const int k0 = q * 4;
        s.hT[(k0 + 0) * STK + v] = m.x;
        s.hT[(k0 + 1) * STK + v] = m.y;
        s.hT[(k0 + 2) * STK + v] = m.z;
        s.hT[(k0 + 3) * STK + v] = m.w;
    }
    __syncthreads();
}

__global__ __launch_bounds__(NT, 2)
void gat_fused_kernel(const float* __restrict__ x,
                      const int* __restrict__ src,
                      const int* __restrict__ dst,
                      const float* __restrict__ b1s, const float* __restrict__ b1d,
                      const float* __restrict__ a1,
                      const float* __restrict__ b2s, const float* __restrict__ b2d,
                      const float* __restrict__ a2,
                      const float* __restrict__ Wg, const float* __restrict__ bg,
                      float* __restrict__ out)
{
    extern __shared__ unsigned char smraw[];
    Smem& s = *reinterpret_cast<Smem*>(smraw);
    const int g = blockIdx.x, tid = threadIdx.x;

    // ---- phase 0: load x transposed, count-sort edges by dst ----
    {
        const float* xg = x + (size_t)g * NV * K1;
        for (int i = tid; i < NV * K1; i += NT) {
            const int row = i >> 7, k = i & 127;
            s.xsT[k * STK + row] = __ldg(&xg[i]);
        }
        const int rs = src[g * NE + tid] - g * NV;
        const int rd = dst[g * NE + tid] - g * NV;
        if (tid < NV) s.cnt[tid] = 0;
        __syncthreads();
        const int p = atomicAdd(&s.cnt[rd], 1);
        __syncthreads();
        if (tid == 0) {
            int acc = 0;
            for (int v = 0; v < NV; v++) { s.startv[v] = acc; acc += s.cnt[v]; }
            s.startv[NV] = acc;
        }
        __syncthreads();
        const int j = s.startv[rd] + p;
        s.esrc[j] = rs;
        s.edst[j] = rd;
    }
    __syncthreads();

    // ---- layer 1 (tf32 tensor-core projections) ----
    gemm_mma<16>(g_wf + WF_W1S, b1s, s.xsT, s.bufA, tid);
    gemm_mma<16>(g_wf + WF_W1D, b1d, s.xsT, s.bufB, tid);
    __syncthreads();
    gat_edge_phase(s, a1, tid);    // NOTE: destroys xsT (Amat alias)

    // ---- layer 2 ----
    gemm_mma<8>(g_wf + WF_W2S, b2s, s.hT, s.bufA, tid);
    gemm_mma<8>(g_wf + WF_W2D, b2d, s.hT, s.bufB, tid);
    __syncthreads();
    gat_edge_phase(s, a2, tid);    // overwrites hT/hN with h2

    // ---- global attention pooling ----
    if (tid < NV) {
        const float4* hN4 = reinterpret_cast<const float4*>(s.hN);
        const float4* wg4 = reinterpret_cast<const float4*>(Wg);
        float gacc = __ldg(&bg[0]);
#pragma unroll
        for (int q = 0; q < 16; q++) {
            const float4 hv = hN4[tid * HNS4 + q];
            const float4 w  = __ldg(&wg4[q]);
            gacc = fmaf(hv.x, w.x, gacc);
            gacc = fmaf(hv.y, w.y, gacc);
            gacc = fmaf(hv.z, w.z, gacc);
            gacc = fmaf(hv.w, w.w, gacc);
        }
        float m = gacc;
#pragma unroll
        for (int o = 16; o; o >>= 1) m = fmaxf(m, __shfl_xor_sync(0xffffffffu, m, o));
        const float ex = __expf(gacc - m);
        float d = ex;
#pragma unroll
        for (int o = 16; o; o >>= 1) d += __shfl_xor_sync(0xffffffffu, d, o);
        s.nalpha[tid] = ex / d;
    }
    __syncthreads();
    if (tid < DH) {
        float r = 0.f;
#pragma unroll
        for (int v = 0; v < NV; v++) r = fmaf(s.nalpha[v], s.hT[tid * STK + v], r);
        out[(size_t)g * DH + tid] = r;
    }
}

extern "C" void kernel_launch(void* const* d_in, const int* in_sizes, int n_in,
                              void* d_out, int out_size)
{
    const float* x   = (const float*)d_in[0];
    const int*   src = (const int*)d_in[1];
    const int*   dst = (const int*)d_in[2];
    const float* W1s = (const float*)d_in[4];
    const float* b1s = (const float*)d_in[5];
    const float* W1d = (const float*)d_in[6];
    const float* b1d = (const float*)d_in[7];
    const float* a1  = (const float*)d_in[8];
    const float* W2s = (const float*)d_in[9];
    const float* b2s = (const float*)d_in[10];
    const float* W2d = (const float*)d_in[11];
    const float* b2d = (const float*)d_in[12];
    const float* a2  = (const float*)d_in[13];
    const float* Wg  = (const float*)d_in[14];
    const float* bg  = (const float*)d_in[15];
    float* out = (float*)d_out;

    prep_w_kernel<<<192, 256>>>(W1s, W1d, W2s, W2d);

    const int smem = (int)sizeof(Smem);
    cudaFuncSetAttribute(gat_fused_kernel,
                         cudaFuncAttributeMaxDynamicSharedMemorySize, smem);
    gat_fused_kernel<<<NGRAPHS, NT, smem>>>(x, src, dst,
                                            b1s, b1d, a1,
                                            b2s, b2d, a2,
                                            Wg, bg, out);
}

// round 13
// speedup vs baseline: 1.5567x; 1.0139x over previous
#include <cuda_runtime.h>
#include <cstdint>

#define NV 32
#define NE 256
#define NH 4
#define DH 64
#define CC 256
#define K1 128
#define K2 64
#define NT 256
#define NGRAPHS 2048

#define SR4 65       // node-major row stride of buf A/B in float4
#define SRF 260
#define XSTR 132     // xs row stride (floats), 132 mod 32 = 4 -> bank-perfect mma A loads
#define XSTR4 33
#define HNS 68       // hN row stride (floats), 68 mod 32 = 4
#define HNS4 17
#define AMS 33       // Amat row stride in float4

// tf32 fragment scratch: [kstep][n8tile][lane][2]
#define WF_W1S 0
#define WF_W1D 32768
#define WF_W2S 65536
#define WF_W2D 81920
__device__ float g_wf[98304];

__global__ void prep_w_kernel(const float* __restrict__ W1s, const float* __restrict__ W1d,
                              const float* __restrict__ W2s, const float* __restrict__ W2d)
{
    const int i = blockIdx.x * blockDim.x + threadIdx.x;
    if (i >= 49152) return;
    const float* W; int base, idx;
    if (i < 16384)      { W = W1s; base = WF_W1S; idx = i; }
    else if (i < 32768) { W = W1d; base = WF_W1D; idx = i - 16384; }
    else if (i < 40960) { W = W2s; base = WF_W2S; idx = i - 32768; }
    else                { W = W2d; base = WF_W2D; idx = i - 40960; }
    const int t   = idx >> 10;
    const int rem = idx & 1023;
    const int n8  = rem >> 5;
    const int l   = rem & 31;
    const int k0  = t * 8 + (l & 3);
    const int n   = n8 * 8 + (l >> 2);
    const float v0 = W[k0 * 256 + n];
    const float v1 = W[(k0 + 4) * 256 + n];
    uint32_t r0, r1;
    asm("cvt.rna.tf32.f32 %0, %1;" : "=r"(r0) : "f"(v0));
    asm("cvt.rna.tf32.f32 %0, %1;" : "=r"(r1) : "f"(v1));
    g_wf[base + idx * 2 + 0] = __uint_as_float(r0);
    g_wf[base + idx * 2 + 1] = __uint_as_float(r1);
}

struct __align__(16) Smem {
    float xs[NV * XSTR];    // 4224 f : x node-major [row][k]; reused as Amat (exactly 4224)
    float bufA[NV * SRF];   // hs node-major
    float bufB[NV * SRF];   // hd node-major; overwritten by aggregation
    float hN[NV * HNS];     // maxpooled h node-major (layer-2 A operand + pooling + readout)
    float logits[NE * NH];
    float aw[CC];
    float mx[NV * NH];
    float den[NV * NH];
    float nalpha[NV];
    int esrc[NE];
    int edst[NE];
    int cnt[NV];
    int startv[NV + 1];
};

__device__ __forceinline__ void fma4(float4& acc, float s, const float4 w) {
    acc.x = fmaf(s, w.x, acc.x);
    acc.y = fmaf(s, w.y, acc.y);
    acc.z = fmaf(s, w.z, acc.z);
    acc.w = fmaf(s, w.w, acc.w);
}

// C[32,256] = A[32,K] @ W[K,256] + b via tf32 mma m16n8k8.
// Warp w owns n8-tiles w*4..w*4+3 over the FULL m=32 (two m-halves in one warp),
// so each B fragment is loaded exactly once. A is node-major with row stride
// ASTR ≡ 4 (mod 32): fragment loads hit 32 distinct banks (4*row + tg).
template <int T, int ASTR>
__device__ __forceinline__ void gemm_mma(const float* __restrict__ Wf,
                                         const float* __restrict__ bias,
                                         const float* __restrict__ As,
                                         float* __restrict__ outb, int tid)
{
    const int w = tid >> 5, lane = tid & 31;
    const int n8b = w * 4;
    const int tg = lane & 3, gid = lane >> 2;

    float acc[4][2][4];
#pragma unroll
    for (int i = 0; i < 4; i++) {
        const int col = (n8b + i) * 8 + tg * 2;
        const float b0 = __ldg(&bias[col]);
        const float b1 = __ldg(&bias[col + 1]);
#pragma unroll
        for (int mg = 0; mg < 2; mg++) {
            acc[i][mg][0] = b0; acc[i][mg][1] = b1;
            acc[i][mg][2] = b0; acc[i][mg][3] = b1;
        }
    }

#pragma unroll
    for (int t = 0; t < T; t++) {
        uint32_t a[2][4];
#pragma unroll
        for (int mg = 0; mg < 2; mg++) {
            const int row = mg * 16 + gid;
            const float f0 = As[row * ASTR + t * 8 + tg];
            const float f1 = As[(row + 8) * ASTR + t * 8 + tg];
            const float f2 = As[row * ASTR + t * 8 + tg + 4];
            const float f3 = As[(row + 8) * ASTR + t * 8 + tg + 4];
            asm("cvt.rna.tf32.f32 %0, %1;" : "=r"(a[mg][0]) : "f"(f0));
            asm("cvt.rna.tf32.f32 %0, %1;" : "=r"(a[mg][1]) : "f"(f1));
            asm("cvt.rna.tf32.f32 %0, %1;" : "=r"(a[mg][2]) : "f"(f2));
            asm("cvt.rna.tf32.f32 %0, %1;" : "=r"(a[mg][3]) : "f"(f3));
        }
        const float2* bf = reinterpret_cast<const float2*>(Wf) + ((t * 32 + n8b) * 32 + lane);
#pragma unroll
        for (int i = 0; i < 4; i++) {
            const float2 bv = __ldg(&bf[i * 32]);
            const uint32_t b0 = __float_as_uint(bv.x);
            const uint32_t b1 = __float_as_uint(bv.y);
#pragma unroll
            for (int mg = 0; mg < 2; mg++) {
                asm volatile(
                    "mma.sync.aligned.m16n8k8.row.col.f32.tf32.tf32.f32 "
                    "{%0,%1,%2,%3}, {%4,%5,%6,%7}, {%8,%9}, {%0,%1,%2,%3};"
                    : "+f"(acc[i][mg][0]), "+f"(acc[i][mg][1]),
                      "+f"(acc[i][mg][2]), "+f"(acc[i][mg][3])
                    : "r"(a[mg][0]), "r"(a[mg][1]), "r"(a[mg][2]), "r"(a[mg][3]),
                      "r"(b0), "r"(b1));
            }
        }
    }

#pragma unroll
    for (int i = 0; i < 4; i++) {
        const int col = (n8b + i) * 8 + tg * 2;
#pragma unroll
        for (int mg = 0; mg < 2; mg++) {
            const int r0 = mg * 16 + gid;
            *reinterpret_cast<float2*>(&outb[r0 * SRF + col]) =
                make_float2(acc[i][mg][0], acc[i][mg][1]);
            *reinterpret_cast<float2*>(&outb[(r0 + 8) * SRF + col]) =
                make_float2(acc[i][mg][2], acc[i][mg][3]);
        }
    }
}

__device__ __forceinline__ float dot_lrelu(const float4 a, const float4 b, const float4 w) {
    float p = 0.f, v;
    v = a.x + b.x; p = fmaf(w.x, v > 0.f ? v : 0.2f * v, p);
    v = a.y + b.y; p = fmaf(w.y, v > 0.f ? v : 0.2f * v, p);
    v = a.z + b.z; p = fmaf(w.z, v > 0.f ? v : 0.2f * v, p);
    v = a.w + b.w; p = fmaf(w.w, v > 0.f ? v : 0.2f * v, p);
    return p;
}

// GATv2 edge phase. bufA = hs, bufB = hd (node-major). Agg overwrites bufB.
// Logits: warp walks its 4 dst-sorted segments with hd + attn register-cached;
// per edge only hs[src] is read (2 contiguous LDS.128).
__device__ __forceinline__ void gat_edge_phase(Smem& s, const float* __restrict__ attn, int tid)
{
    s.aw[tid] = __ldg(&attn[tid]);
    __syncthreads();

    float4* bufA4 = reinterpret_cast<float4*>(s.bufA);
    float4* bufB4 = reinterpret_cast<float4*>(s.bufB);
    const float4* aw4 = reinterpret_cast<const float4*>(s.aw);
    float* Amat = s.xs;                       // alias: 32 x AMS float4 = 4224 floats
    float4* Amat4 = reinterpret_cast<float4*>(Amat);

    const int wid = tid >> 5, lane = tid & 31;

    // --- logits by dst segment ---
    {
        const float4 awr0 = aw4[lane];
        const float4 awr1 = aw4[32 + lane];
#pragma unroll
        for (int si = 0; si < 4; si++) {
            const int v = wid * 4 + si;
            const int e0 = s.startv[v], e1 = s.startv[v + 1];
            if (e0 == e1) continue;
            const float4 hd0 = bufB4[v * SR4 + lane];
            const float4 hd1 = bufB4[v * SR4 + 32 + lane];
            for (int e = e0; e < e1; e++) {
                const int ss = s.esrc[e];
                const float4 sa0 = bufA4[ss * SR4 + lane];
                const float4 sa1 = bufA4[ss * SR4 + 32 + lane];
                float p0 = dot_lrelu(sa0, hd0, awr0);
                float p1 = dot_lrelu(sa1, hd1, awr1);
#pragma unroll
                for (int o = 8; o; o >>= 1) {
                    p0 += __shfl_xor_sync(0xffffffffu, p0, o);
                    p1 += __shfl_xor_sync(0xffffffffu, p1, o);
                }
                if ((lane & 15) == 0) {
                    const int hh = lane >> 4;       // 0 or 1
                    s.logits[e * NH + hh]     = p0; // heads 0/1
                    s.logits[e * NH + 2 + hh] = p1; // heads 2/3
                }
            }
        }
    }
    __syncthreads();

    // --- per (node, head) max & exp-sum; other half zeroes Amat ---
    if (tid < NV * NH) {
        const int v = tid >> 2, h = tid & 3;
        const int e0 = s.startv[v], e1 = s.startv[v + 1];
        float m = -1e30f;
        for (int j = e0; j < e1; j++) m = fmaxf(m, s.logits[j * NH + h]);
        float d = 0.f;
        for (int j = e0; j < e1; j++) d += __expf(s.logits[j * NH + h] - m);
        s.mx[tid]  = m;
        s.den[tid] = (d == 0.f) ? 1.f : d;
    } else {
        const float4 z = make_float4(0.f, 0.f, 0.f, 0.f);
        for (int i = tid - 128; i < NV * AMS; i += 128) Amat4[i] = z;
    }
    __syncthreads();

    // --- per-edge alpha -> dense Amat[dst][src] (float4 = 4 heads) ---
    {
        const int e = tid;
        const int dd = s.edst[e], ss = s.esrc[e];
        const float4 lg  = *reinterpret_cast<const float4*>(&s.logits[e * NH]);
        const float4 mxv = *reinterpret_cast<const float4*>(&s.mx[dd * NH]);
        const float4 dnv = *reinterpret_cast<const float4*>(&s.den[dd * NH]);
        float* am = Amat + (dd * AMS + ss) * 4;
        atomicAdd(am + 0, __expf(lg.x - mxv.x) / dnv.x);
        atomicAdd(am + 1, __expf(lg.y - mxv.y) / dnv.y);
        atomicAdd(am + 2, __expf(lg.z - mxv.z) / dnv.z);
        atomicAdd(am + 3, __expf(lg.w - mxv.w) / dnv.w);
    }
    __syncthreads();

    // --- dense aggregation: bufB[v] = sum_u Amat[v][u] (per head) * hs[u] ---
    {
        const int v = tid >> 3;
        const int l = tid & 7;
        float4 acc[8];
#pragma unroll
        for (int blk = 0; blk < 8; blk++) acc[blk] = make_float4(0.f, 0.f, 0.f, 0.f);
        const float4* AmV = Amat4 + v * AMS;
        for (int u = 0; u < NV; u++) {
            const float4 a4 = AmV[u];
            const bool nz = (a4.x != 0.f) | (a4.y != 0.f) | (a4.z != 0.f) | (a4.w != 0.f);
            if (!__any_sync(0xffffffffu, nz)) continue;
            const float4* p = bufA4 + u * SR4;
#pragma unroll
            for (int blk = 0; blk < 8; blk++) {
                const int h = blk >> 1;
                const float a = (h == 0) ? a4.x : (h == 1) ? a4.y : (h == 2) ? a4.z : a4.w;
                fma4(acc[blk], a, p[blk * 8 + l]);
            }
        }
#pragma unroll
        for (int blk = 0; blk < 8; blk++) bufB4[v * SR4 + blk * 8 + l] = acc[blk];
    }
    __syncthreads();

    // --- head maxpool -> hN[v][k] only ---
    float4* hN4 = reinterpret_cast<float4*>(s.hN);
    for (int i = tid; i < NV * DH / 4; i += NT) {
        const int v = i >> 4, q = i & 15;
        float4 m = bufB4[v * SR4 + q];
#pragma unroll
        for (int h = 1; h < NH; h++) {
            const float4 t = bufB4[v * SR4 + h * 16 + q];
            m.x = fmaxf(m.x, t.x); m.y = fmaxf(m.y, t.y);
            m.z = fmaxf(m.z, t.z); m.w = fmaxf(m.w, t.w);
        }
        hN4[v * HNS4 + q] = m;
    }
    __syncthreads();
}

__global__ __launch_bounds__(NT, 2)
void gat_fused_kernel(const float* __restrict__ x,
                      const int* __restrict__ src,
                      const int* __restrict__ dst,
                      const float* __restrict__ b1s, const float* __restrict__ b1d,
                      const float* __restrict__ a1,
                      const float* __restrict__ b2s, const float* __restrict__ b2d,
                      const float* __restrict__ a2,
                      const float* __restrict__ Wg, const float* __restrict__ bg,
                      float* __restrict__ out)
{
    extern __shared__ unsigned char smraw[];
    Smem& s = *reinterpret_cast<Smem*>(smraw);
    const int g = blockIdx.x, tid = threadIdx.x;

    // ---- phase 0: load x node-major (coalesced, conflict-free), count-sort edges ----
    {
        const float4* xg4 = reinterpret_cast<const float4*>(x + (size_t)g * NV * K1);
        float4* xs4 = reinterpret_cast<float4*>(s.xs);
        for (int i = tid; i < NV * K1 / 4; i += NT) {
            const int row = i >> 5, k4 = i & 31;
            xs4[row * XSTR4 + k4] = __ldg(&xg4[i]);
        }
        const int rs = src[g * NE + tid] - g * NV;
        const int rd = dst[g * NE + tid] - g * NV;
        if (tid < NV) s.cnt[tid] = 0;
        __syncthreads();
        const int p = atomicAdd(&s.cnt[rd], 1);
        __syncthreads();
        if (tid == 0) {
            int acc = 0;
            for (int v = 0; v < NV; v++) { s.startv[v] = acc; acc += s.cnt[v]; }
            s.startv[NV] = acc;
        }
        __syncthreads();
        const int j = s.startv[rd] + p;
        s.esrc[j] = rs;
        s.edst[j] = rd;
    }
    __syncthreads();

    // ---- layer 1 (tf32 mma; A = xs node-major) ----
    gemm_mma<16, XSTR>(g_wf + WF_W1S, b1s, s.xs, s.bufA, tid);
    gemm_mma<16, XSTR>(g_wf + WF_W1D, b1d, s.xs, s.bufB, tid);
    __syncthreads();
    gat_edge_phase(s, a1, tid);    // destroys xs (Amat alias); writes hN

    // ---- layer 2 (A = hN node-major) ----
    gemm_mma<8, HNS>(g_wf + WF_W2S, b2s, s.hN, s.bufA, tid);
    gemm_mma<8, HNS>(g_wf + WF_W2D, b2d, s.hN, s.bufB, tid);
    __syncthreads();
    gat_edge_phase(s, a2, tid);    // overwrites hN with h2

    // ---- global attention pooling ----
    if (tid < NV) {
        const float4* hN4 = reinterpret_cast<const float4*>(s.hN);
        const float4* wg4 = reinterpret_cast<const float4*>(Wg);
        float gacc = __ldg(&bg[0]);
#pragma unroll
        for (int q = 0; q < 16; q++) {
            const float4 hv = hN4[tid * HNS4 + q];
            const float4 w  = __ldg(&wg4[q]);
            gacc = fmaf(hv.x, w.x, gacc);
            gacc = fmaf(hv.y, w.y, gacc);
            gacc = fmaf(hv.z, w.z, gacc);
            gacc = fmaf(hv.w, w.w, gacc);
        }
        float m = gacc;
#pragma unroll
        for (int o = 16; o; o >>= 1) m = fmaxf(m, __shfl_xor_sync(0xffffffffu, m, o));
        const float ex = __expf(gacc - m);
        float d = ex;
#pragma unroll
        for (int o = 16; o; o >>= 1) d += __shfl_xor_sync(0xffffffffu, d, o);
        s.nalpha[tid] = ex / d;
    }
    __syncthreads();
    if (tid < DH) {
        float r = 0.f;
#pragma unroll
        for (int v = 0; v < NV; v++) r = fmaf(s.nalpha[v], s.hN[v * HNS + tid], r);
        out[(size_t)g * DH + tid] = r;
    }
}

extern "C" void kernel_launch(void* const* d_in, const int* in_sizes, int n_in,
                              void* d_out, int out_size)
{
    const float* x   = (const float*)d_in[0];
    const int*   src = (const int*)d_in[1];
    const int*   dst = (const int*)d_in[2];
    const float* W1s = (const float*)d_in[4];
    const float* b1s = (const float*)d_in[5];
    const float* W1d = (const float*)d_in[6];
    const float* b1d = (const float*)d_in[7];
    const float* a1  = (const float*)d_in[8];
    const float* W2s = (const float*)d_in[9];
    const float* b2s = (const float*)d_in[10];
    const float* W2d = (const float*)d_in[11];
    const float* b2d = (const float*)d_in[12];
    const float* a2  = (const float*)d_in[13];
    const float* Wg  = (const float*)d_in[14];
    const float* bg  = (const float*)d_in[15];
    float* out = (float*)d_out;

    prep_w_kernel<<<192, 256>>>(W1s, W1d, W2s, W2d);

    const int smem = (int)sizeof(Smem);
    cudaFuncSetAttribute(gat_fused_kernel,
                         cudaFuncAttributeMaxDynamicSharedMemorySize, smem);
    gat_fused_kernel<<<NGRAPHS, NT, smem>>>(x, src, dst,
                                            b1s, b1d, a1,
                                            b2s, b2d, a2,
                                            Wg, bg, out);
}